// round 5
// baseline (speedup 1.0000x reference)
#include <cuda_runtime.h>
#include <cuda_bf16.h>

// Problem shape (fixed by the dataset)
#define BB 32
#define TT 2048
#define DD 512
#define D4 (DD / 4)       // 128 float4 per (b,t) row
#define G  2048           // pass1 grid size (single wave on 148 SMs)

// Scratch (device globals — no allocation allowed in kernel_launch)
__device__ float4 g_part[(G + BB) * D4]; // slot (g+b): per-(block,b,d4) sum of (p-t)
__device__ float  g_wl[G];               // per-block word-loss partial
__device__ float  g_sent[BB];            // per-b sentence loss (mean over D)

__device__ __forceinline__ float sl1(float d) {
    float ad = fabsf(d);
    return (ad < 1.0f) ? (0.5f * d * d) : (ad - 0.5f);
}

// Warp-scan prefix of lens into shared P[0..BB]; returns nothing (P shared).
__device__ __forceinline__ void build_prefix(const int* __restrict__ lens, int* P) {
    int tid = threadIdx.x;
    if (tid < 32) {
        int x = lens[tid];
        #pragma unroll
        for (int o = 1; o < 32; o <<= 1) {
            int y = __shfl_up_sync(0xffffffffu, x, o);
            if (tid >= o) x += y;
        }
        P[tid + 1] = x;
        if (tid == 0) P[0] = 0;
    }
    __syncthreads();
}

// ---------------------------------------------------------------------------
// Pass 1: evenly partition the W = sum(len) valid rows across G blocks.
// Each block streams a contiguous slice of valid rows; thread tid owns d4 col.
// ---------------------------------------------------------------------------
__global__ __launch_bounds__(128) void pass1(const float4* __restrict__ p,
                                             const float4* __restrict__ q,
                                             const int* __restrict__ lens) {
    __shared__ int P[BB + 1];
    build_prefix(lens, P);
    int tid = threadIdx.x;
    long long W = P[BB];
    long long g = blockIdx.x;

    int w0 = (int)(g * W / G);
    int w1 = (int)((g + 1) * W / G);

    float wl = 0.f;

    // find batch containing w0
    int b = 0;
    while (b < BB - 1 && P[b + 1] <= w0) ++b;

    int w = w0;
    while (w < w1) {
        int e = min(w1, P[b + 1]);       // end of this batch's run in our slice
        int n = e - w;
        if (n > 0) {
            int t = w - P[b];
            const float4* __restrict__ pp = p + ((size_t)b * TT + t) * D4 + tid;
            const float4* __restrict__ pq = q + ((size_t)b * TT + t) * D4 + tid;
            float4 sd = make_float4(0.f, 0.f, 0.f, 0.f);
            #pragma unroll 8
            for (int i = 0; i < n; ++i) {
                float4 a  = __ldcs(pp + (size_t)i * D4);
                float4 bt = __ldcs(pq + (size_t)i * D4);
                float dx = a.x - bt.x, dy = a.y - bt.y;
                float dz = a.z - bt.z, dw = a.w - bt.w;
                sd.x += dx; sd.y += dy; sd.z += dz; sd.w += dw;
                wl += sl1(dx) + sl1(dy) + sl1(dz) + sl1(dw);
            }
            g_part[(blockIdx.x + b) * D4 + tid] = sd;   // staircase slot, injective
        }
        w = e; ++b;
    }

    // block-reduce word loss (4 warps)
    #pragma unroll
    for (int o = 16; o > 0; o >>= 1) wl += __shfl_down_sync(0xffffffffu, wl, o);
    __shared__ float s[4];
    if ((tid & 31) == 0) s[tid >> 5] = wl;
    __syncthreads();
    if (tid == 0) g_wl[blockIdx.x] = s[0] + s[1] + s[2] + s[3];
}

// ---------------------------------------------------------------------------
// Pass 2: per-b sentence loss. grid = BB, block = 128 (thread tid owns d4 col).
// ---------------------------------------------------------------------------
__global__ __launch_bounds__(128) void pass2(const int* __restrict__ lens) {
    __shared__ int P[BB + 1];
    build_prefix(lens, P);
    int b   = blockIdx.x;
    int tid = threadIdx.x;

    long long W = P[BB];
    int wlo = P[b], whi = P[b + 1];     // this batch's item range (len >= 1)

    // first/last block overlapping [wlo, whi)
    long long gf = (long long)wlo * G / W;
    while (gf > 0 && gf * W / G > wlo) --gf;
    while ((gf + 1) * W / G <= wlo) ++gf;
    long long gl = (long long)(whi - 1) * G / W;
    while (gl > 0 && gl * W / G > (whi - 1)) --gl;
    while ((gl + 1) * W / G <= (whi - 1)) ++gl;

    float4 sd = make_float4(0.f, 0.f, 0.f, 0.f);
    for (long long g = gf; g <= gl; ++g) {
        int a0 = (int)(g * W / G), a1 = (int)((g + 1) * W / G);
        if (a1 <= wlo || a0 >= whi || a0 == a1) continue;  // no overlap / empty block
        float4 v = g_part[((int)g + b) * D4 + tid];
        sd.x += v.x; sd.y += v.y; sd.z += v.z; sd.w += v.w;
    }

    float inv_len = 1.0f / (float)lens[b];
    float v = sl1(sd.x * inv_len) + sl1(sd.y * inv_len)
            + sl1(sd.z * inv_len) + sl1(sd.w * inv_len);

    #pragma unroll
    for (int o = 16; o > 0; o >>= 1) v += __shfl_down_sync(0xffffffffu, v, o);
    __shared__ float s[4];
    if ((tid & 31) == 0) s[tid >> 5] = v;
    __syncthreads();
    if (tid == 0) g_sent[b] = (s[0] + s[1] + s[2] + s[3]) / (float)DD;
}

// ---------------------------------------------------------------------------
// Pass 3: final fold. grid = 1, block = 256.
// ---------------------------------------------------------------------------
__global__ __launch_bounds__(256) void pass3(const int* __restrict__ lens,
                                             float* __restrict__ out) {
    int tid = threadIdx.x;

    float wl = 0.f;
    #pragma unroll
    for (int i = tid; i < G; i += 256) wl += g_wl[i];

    float sent = (tid < BB) ? g_sent[tid] : 0.f;
    float lsum = (tid < BB) ? (float)lens[tid] : 0.f;

    __shared__ float swl[8], ssn[8], sln[8];
    float a = wl, bv = sent, cv = lsum;
    #pragma unroll
    for (int o = 16; o > 0; o >>= 1) {
        a  += __shfl_down_sync(0xffffffffu, a,  o);
        bv += __shfl_down_sync(0xffffffffu, bv, o);
        cv += __shfl_down_sync(0xffffffffu, cv, o);
    }
    int w = tid >> 5;
    if ((tid & 31) == 0) { swl[w] = a; ssn[w] = bv; sln[w] = cv; }
    __syncthreads();

    if (tid == 0) {
        float wl_tot = 0.f, sn_tot = 0.f, ln_tot = 0.f;
        #pragma unroll
        for (int i = 0; i < 8; ++i) { wl_tot += swl[i]; sn_tot += ssn[i]; ln_tot += sln[i]; }
        float n_valid   = ln_tot * (float)DD;
        out[0] = wl_tot / n_valid + sn_tot / (float)BB;
    }
}

extern "C" void kernel_launch(void* const* d_in, const int* in_sizes, int n_in,
                              void* d_out, int out_size) {
    const float4* preds   = (const float4*)d_in[0];
    const float4* targets = (const float4*)d_in[1];
    const int*    lens    = (const int*)d_in[2];
    float*        out     = (float*)d_out;

    pass1<<<G, 128>>>(preds, targets, lens);
    pass2<<<BB, 128>>>(lens);
    pass3<<<1, 256>>>(lens, out);
}

// round 8
// speedup vs baseline: 1.2904x; 1.2904x over previous
#include <cuda_runtime.h>
#include <cuda_bf16.h>

// Problem shape (fixed by the dataset)
#define BB 32
#define TT 2048
#define DD 512
#define D4 (DD / 4)            // 128 float4 per (b,t) row
#define NCHUNK 256
#define CHUNK (TT / NCHUNK)    // 8 timesteps per block
#define GRID1 (BB * NCHUNK)    // 8192 pass1 blocks

// Scratch (device globals — no allocation allowed in kernel_launch)
__device__ float4 g_part[BB * NCHUNK * D4];  // per-(b,chunk,d4) sum of (p-t); only valid chunks written
__device__ float  g_wl[GRID1];               // per-block word-loss partial
__device__ float  g_sp[BB * 4];              // per-(b,d-slice) sentence partials
__device__ int    g_cnt;                     // last-block ticket (zero-init; self-resetting)

__device__ __forceinline__ float sl1(float d) {
    float ad = fabsf(d);
    return (ad < 1.0f) ? (0.5f * d * d) : (ad - 0.5f);
}

// ---------------------------------------------------------------------------
// Pass 1: stream preds/targets once. grid = 8192, block = 128.
// Thread tid owns float4 column tid (d = 4*tid .. 4*tid+3).
// ---------------------------------------------------------------------------
__global__ __launch_bounds__(128) void pass1(const float4* __restrict__ p,
                                             const float4* __restrict__ q,
                                             const int* __restrict__ lens) {
    int b   = blockIdx.x >> 8;           // / NCHUNK
    int c   = blockIdx.x & (NCHUNK - 1);
    int tid = threadIdx.x;

    int len = __ldg(lens + b);
    int t0  = c * CHUNK;
    int t1  = min(t0 + CHUNK, len);

    float wl = 0.f;

    if (t1 > t0) {
        float4 sd = make_float4(0.f, 0.f, 0.f, 0.f);
        const float4* __restrict__ pp = p + ((size_t)b * TT + t0) * D4 + tid;
        const float4* __restrict__ pq = q + ((size_t)b * TT + t0) * D4 + tid;
        int n = t1 - t0;
        #pragma unroll 8
        for (int i = 0; i < n; ++i) {
            float4 a  = __ldg(pp + (size_t)i * D4);
            float4 bt = __ldg(pq + (size_t)i * D4);
            float dx = a.x - bt.x, dy = a.y - bt.y;
            float dz = a.z - bt.z, dw = a.w - bt.w;
            sd.x += dx; sd.y += dy; sd.z += dz; sd.w += dw;
            wl += sl1(dx) + sl1(dy) + sl1(dz) + sl1(dw);
        }
        g_part[(size_t)blockIdx.x * D4 + tid] = sd;
    }

    // block-reduce word loss (4 warps)
    #pragma unroll
    for (int o = 16; o > 0; o >>= 1) wl += __shfl_down_sync(0xffffffffu, wl, o);
    __shared__ float s[4];
    if ((tid & 31) == 0) s[tid >> 5] = wl;
    __syncthreads();
    if (tid == 0) g_wl[blockIdx.x] = s[0] + s[1] + s[2] + s[3];
}

// ---------------------------------------------------------------------------
// Pass 2 (+ fused final fold): grid = BB*4 = 128, block = 128.
// Block (b, slice): 32 float4 cols; 4 chunk-lanes of 32 threads split the chunks.
// Last block to finish folds everything and writes out[0]. No spin-waits:
// the last ticket holder simply does the extra work (deadlock-free).
// ---------------------------------------------------------------------------
__global__ __launch_bounds__(128) void pass2(const int* __restrict__ lens,
                                             float* __restrict__ out) {
    int b     = blockIdx.x >> 2;
    int slice = blockIdx.x & 3;
    int tid   = threadIdx.x;
    int col   = slice * 32 + (tid & 31);    // float4 column in [0,128)
    int r     = tid >> 5;                   // chunk-lane 0..3

    int len  = __ldg(lens + b);
    int cmax = (len + CHUNK - 1) / CHUNK;   // only valid chunks were written

    float4 sd = make_float4(0.f, 0.f, 0.f, 0.f);
    const float4* __restrict__ base = g_part + (size_t)b * NCHUNK * D4 + col;
    for (int c = r; c < cmax; c += 4) {
        float4 a = base[(size_t)c * D4];
        sd.x += a.x; sd.y += a.y; sd.z += a.z; sd.w += a.w;
    }

    __shared__ float4 sh[128];
    __shared__ int    is_last;
    sh[tid] = sd;
    __syncthreads();

    if (tid < 32) {
        float4 a0 = sh[tid], a1 = sh[tid + 32], a2 = sh[tid + 64], a3 = sh[tid + 96];
        float inv_len = 1.0f / (float)len;
        float v = sl1((a0.x + a1.x + a2.x + a3.x) * inv_len)
                + sl1((a0.y + a1.y + a2.y + a3.y) * inv_len)
                + sl1((a0.z + a1.z + a2.z + a3.z) * inv_len)
                + sl1((a0.w + a1.w + a2.w + a3.w) * inv_len);
        #pragma unroll
        for (int o = 16; o > 0; o >>= 1) v += __shfl_down_sync(0xffffffffu, v, o);
        if (tid == 0) {
            g_sp[blockIdx.x] = v;
            __threadfence();
            int t = atomicAdd(&g_cnt, 1);
            is_last = (t == BB * 4 - 1);
        }
    }
    __syncthreads();

    if (is_last) {
        __threadfence();   // acquire: make all blocks' g_sp / g_wl visible
        // word-loss partials: 8192 floats
        float wl = 0.f;
        for (int i = tid; i < GRID1; i += 128) wl += g_wl[i];
        // sentence partials: 128 floats; lens: 32 ints
        float sp = g_sp[tid];
        float ls = (tid < BB) ? (float)__ldg(lens + tid) : 0.f;

        float a = wl, bv = sp, cv = ls;
        #pragma unroll
        for (int o = 16; o > 0; o >>= 1) {
            a  += __shfl_down_sync(0xffffffffu, a,  o);
            bv += __shfl_down_sync(0xffffffffu, bv, o);
            cv += __shfl_down_sync(0xffffffffu, cv, o);
        }
        __shared__ float swl[4], ssn[4], sln[4];
        if ((tid & 31) == 0) { swl[tid >> 5] = a; ssn[tid >> 5] = bv; sln[tid >> 5] = cv; }
        __syncthreads();
        if (tid == 0) {
            float wl_tot = swl[0] + swl[1] + swl[2] + swl[3];
            float sn_tot = ssn[0] + ssn[1] + ssn[2] + ssn[3];
            float ln_tot = sln[0] + sln[1] + sln[2] + sln[3];
            float n_valid = ln_tot * (float)DD;
            out[0] = wl_tot / n_valid + (sn_tot / (float)DD) / (float)BB;
            g_cnt = 0;   // reset for next graph replay (unique last writer)
        }
    }
}

extern "C" void kernel_launch(void* const* d_in, const int* in_sizes, int n_in,
                              void* d_out, int out_size) {
    const float4* preds   = (const float4*)d_in[0];
    const float4* targets = (const float4*)d_in[1];
    const int*    lens    = (const int*)d_in[2];
    float*        out     = (float*)d_out;

    pass1<<<GRID1, 128>>>(preds, targets, lens);
    pass2<<<BB * 4, 128>>>(lens, out);
}

// round 9
// speedup vs baseline: 1.4919x; 1.1562x over previous
#include <cuda_runtime.h>
#include <cuda_bf16.h>

// Problem shape (fixed by the dataset)
#define BB 32
#define TT 2048
#define DD 512
#define D4 (DD / 4)            // 128 float4 per (b,t) row
#define NCHUNK 256
#define CHUNK (TT / NCHUNK)    // 8 timesteps per pass1 block
#define GRID1 (BB * NCHUNK)    // 8192 pass1 blocks
#define NSLAB 32               // 8 chunks per slab
#define SLAB  8

// Scratch (device globals — no allocation allowed in kernel_launch)
__device__ float4 g_part [BB * NCHUNK * D4]; // per-(b,chunk,d4) sum of (p-t); valid chunks only
__device__ float4 g_part2[BB * NSLAB * D4];  // per-(b,slab,d4) sum; valid slabs only
__device__ float  g_wl [GRID1];              // per-pass1-block word-loss partial
__device__ float  g_wl2[BB * NSLAB];         // per-slab word-loss partial (always written)
__device__ float  g_sp [BB * 4];             // per-(b,d-slice) sentence partials
__device__ int    g_cnt;                     // last-block ticket (zero-init; self-resetting)

__device__ __forceinline__ float sl1(float d) {
    float ad = fabsf(d);
    return (ad < 1.0f) ? (0.5f * d * d) : (ad - 0.5f);
}

// ---------------------------------------------------------------------------
// Pass 1: stream preds/targets once. grid = 8192, block = 128.
// Thread tid owns float4 column tid (d = 4*tid .. 4*tid+3).
// ---------------------------------------------------------------------------
__global__ __launch_bounds__(128) void pass1(const float4* __restrict__ p,
                                             const float4* __restrict__ q,
                                             const int* __restrict__ lens) {
    int b   = blockIdx.x >> 8;           // / NCHUNK
    int c   = blockIdx.x & (NCHUNK - 1);
    int tid = threadIdx.x;

    int len = __ldg(lens + b);
    int t0  = c * CHUNK;
    int t1  = min(t0 + CHUNK, len);

    float wl = 0.f;

    if (t1 > t0) {
        float4 sd = make_float4(0.f, 0.f, 0.f, 0.f);
        const float4* __restrict__ pp = p + ((size_t)b * TT + t0) * D4 + tid;
        const float4* __restrict__ pq = q + ((size_t)b * TT + t0) * D4 + tid;
        int n = t1 - t0;
        #pragma unroll 8
        for (int i = 0; i < n; ++i) {
            float4 a  = __ldg(pp + (size_t)i * D4);
            float4 bt = __ldg(pq + (size_t)i * D4);
            float dx = a.x - bt.x, dy = a.y - bt.y;
            float dz = a.z - bt.z, dw = a.w - bt.w;
            sd.x += dx; sd.y += dy; sd.z += dz; sd.w += dw;
            wl += sl1(dx) + sl1(dy) + sl1(dz) + sl1(dw);
        }
        g_part[(size_t)blockIdx.x * D4 + tid] = sd;
    }

    // block-reduce word loss (4 warps)
    #pragma unroll
    for (int o = 16; o > 0; o >>= 1) wl += __shfl_down_sync(0xffffffffu, wl, o);
    __shared__ float s[4];
    if ((tid & 31) == 0) s[tid >> 5] = wl;
    __syncthreads();
    if (tid == 0) g_wl[blockIdx.x] = s[0] + s[1] + s[2] + s[3];
}

// ---------------------------------------------------------------------------
// Pass 2a: fold 8-chunk slabs. grid = BB*NSLAB = 1024, block = 128 (tid = col).
// Also folds the matching 8-entry g_wl strip (always, so g_wl2 is dense).
// ---------------------------------------------------------------------------
__global__ __launch_bounds__(128) void pass2a(const int* __restrict__ lens) {
    int b   = blockIdx.x >> 5;
    int j   = blockIdx.x & (NSLAB - 1);
    int tid = threadIdx.x;
    int c0  = j * SLAB;

    // word-loss strip fold (entries beyond cmax are exact zeros from pass1)
    if (tid < 32) {
        float w = (tid < SLAB) ? g_wl[b * NCHUNK + c0 + tid] : 0.f;
        #pragma unroll
        for (int o = 4; o > 0; o >>= 1) w += __shfl_down_sync(0xffffffffu, w, o);
        if (tid == 0) g_wl2[blockIdx.x] = w;
    }

    int len  = __ldg(lens + b);
    int cmax = (len + CHUNK - 1) / CHUNK;
    int n    = min(SLAB, cmax - c0);
    if (n <= 0) return;                      // slab fully invalid: nothing written

    const float4* __restrict__ base = g_part + ((size_t)(b * NCHUNK + c0)) * D4 + tid;
    float4 sd = make_float4(0.f, 0.f, 0.f, 0.f);
    #pragma unroll 8
    for (int k = 0; k < n; ++k) {
        float4 a = base[(size_t)k * D4];
        sd.x += a.x; sd.y += a.y; sd.z += a.z; sd.w += a.w;
    }
    g_part2[(size_t)blockIdx.x * D4 + tid] = sd;
}

// ---------------------------------------------------------------------------
// Pass 2b (+ fused final fold): grid = BB*4 = 128, block = 128.
// Block (b, slice): 32 float4 cols; 4 slab-lanes of 32 threads split ≤32 slabs.
// Last block folds g_sp + g_wl2 + lens and writes out[0]. No spin-waits.
// ---------------------------------------------------------------------------
__global__ __launch_bounds__(128) void pass2b(const int* __restrict__ lens,
                                              float* __restrict__ out) {
    int b     = blockIdx.x >> 2;
    int slice = blockIdx.x & 3;
    int tid   = threadIdx.x;
    int col   = slice * 32 + (tid & 31);    // float4 column in [0,128)
    int r     = tid >> 5;                   // slab-lane 0..3

    int len   = __ldg(lens + b);
    int cmax  = (len + CHUNK - 1) / CHUNK;
    int smax  = (cmax + SLAB - 1) / SLAB;   // valid slabs (all written by pass2a)

    float4 sd = make_float4(0.f, 0.f, 0.f, 0.f);
    const float4* __restrict__ base = g_part2 + (size_t)b * NSLAB * D4 + col;
    #pragma unroll 8
    for (int j = r; j < smax; j += 4) {
        float4 a = base[(size_t)j * D4];
        sd.x += a.x; sd.y += a.y; sd.z += a.z; sd.w += a.w;
    }

    __shared__ float4 sh[128];
    __shared__ int    is_last;
    sh[tid] = sd;
    __syncthreads();

    if (tid < 32) {
        float4 a0 = sh[tid], a1 = sh[tid + 32], a2 = sh[tid + 64], a3 = sh[tid + 96];
        float inv_len = 1.0f / (float)len;
        float v = sl1((a0.x + a1.x + a2.x + a3.x) * inv_len)
                + sl1((a0.y + a1.y + a2.y + a3.y) * inv_len)
                + sl1((a0.z + a1.z + a2.z + a3.z) * inv_len)
                + sl1((a0.w + a1.w + a2.w + a3.w) * inv_len);
        #pragma unroll
        for (int o = 16; o > 0; o >>= 1) v += __shfl_down_sync(0xffffffffu, v, o);
        if (tid == 0) {
            g_sp[blockIdx.x] = v;
            __threadfence();
            int t = atomicAdd(&g_cnt, 1);
            is_last = (t == BB * 4 - 1);
        }
    }
    __syncthreads();

    if (is_last) {
        __threadfence();   // acquire: all blocks' g_sp visible (g_wl2 from prior kernel)
        float wl = 0.f;
        #pragma unroll
        for (int i = tid; i < BB * NSLAB; i += 128) wl += g_wl2[i];   // 8 each
        float sp = g_sp[tid];
        float ls = (tid < BB) ? (float)__ldg(lens + tid) : 0.f;

        float a = wl, bv = sp, cv = ls;
        #pragma unroll
        for (int o = 16; o > 0; o >>= 1) {
            a  += __shfl_down_sync(0xffffffffu, a,  o);
            bv += __shfl_down_sync(0xffffffffu, bv, o);
            cv += __shfl_down_sync(0xffffffffu, cv, o);
        }
        __shared__ float swl[4], ssn[4], sln[4];
        if ((tid & 31) == 0) { swl[tid >> 5] = a; ssn[tid >> 5] = bv; sln[tid >> 5] = cv; }
        __syncthreads();
        if (tid == 0) {
            float wl_tot = swl[0] + swl[1] + swl[2] + swl[3];
            float sn_tot = ssn[0] + ssn[1] + ssn[2] + ssn[3];
            float ln_tot = sln[0] + sln[1] + sln[2] + sln[3];
            float n_valid = ln_tot * (float)DD;
            out[0] = wl_tot / n_valid + (sn_tot / (float)DD) / (float)BB;
            g_cnt = 0;   // reset for next graph replay (unique last writer)
        }
    }
}

extern "C" void kernel_launch(void* const* d_in, const int* in_sizes, int n_in,
                              void* d_out, int out_size) {
    const float4* preds   = (const float4*)d_in[0];
    const float4* targets = (const float4*)d_in[1];
    const int*    lens    = (const int*)d_in[2];
    float*        out     = (float*)d_out;

    pass1<<<GRID1, 128>>>(preds, targets, lens);
    pass2a<<<BB * NSLAB, 128>>>(lens);
    pass2b<<<BB * 4, 128>>>(lens, out);
}

// round 13
// speedup vs baseline: 1.5054x; 1.0091x over previous
#include <cuda_runtime.h>
#include <cuda_bf16.h>

// Problem shape (fixed by the dataset)
#define BB 32
#define TT 2048
#define DD 512
#define D4 (DD / 4)            // 128 float4 per (b,t) row
#define NCHUNK 256
#define CHUNK (TT / NCHUNK)    // 8 timesteps per block
#define GRID1 (BB * NCHUNK)    // 8192 blocks
#define NSLAB 32
#define SLAB  8                // chunks per slab

// Scratch (device globals, zero-initialized; no allocation in kernel_launch).
// Invariant: entries for invalid chunks/slabs are NEVER written -> stay 0.0
// across all graph replays, so folds read unconditionally.
__device__ float4 g_part [BB * NCHUNK * D4];  // per-(b,chunk,d4) sum of (p-t)
__device__ float4 g_part2[BB * NSLAB * D4];   // per-(b,slab,d4) sum (dense)
__device__ float  g_wl  [GRID1];              // per-chunk-block word-loss partial
__device__ float  g_wl2 [BB * NSLAB];         // per-slab word-loss partial (dense)
__device__ float  g_wlb [BB];                 // per-b word-loss
__device__ float  g_sent[BB];                 // per-b sentence loss (mean over D)
__device__ int    g_c1[BB * NSLAB];           // slab tickets   (self-resetting)
__device__ int    g_c2[BB];                   // batch tickets  (self-resetting)
__device__ int    g_c3;                       // global ticket  (self-resetting)

__device__ __forceinline__ float sl1(float d) {
    float ad = fabsf(d);
    return (ad < 1.0f) ? (0.5f * d * d) : (ad - 0.5f);
}

__global__ __launch_bounds__(128) void fused(const float4* __restrict__ p,
                                             const float4* __restrict__ q,
                                             const int* __restrict__ lens,
                                             float* __restrict__ out) {
    const int b   = blockIdx.x >> 8;           // batch
    const int c   = blockIdx.x & (NCHUNK - 1); // chunk
    const int j   = c >> 3;                    // slab
    const int tid = threadIdx.x;

    __shared__ float s4[4];
    __shared__ int   flag;

    const int len = __ldg(lens + b);
    const int t0  = c * CHUNK;
    const int t1  = min(t0 + CHUNK, len);

    // ---------------- Phase A: stream my chunk ----------------
    float wl = 0.f;
    if (t1 > t0) {
        float4 sd = make_float4(0.f, 0.f, 0.f, 0.f);
        const float4* __restrict__ pp = p + ((size_t)b * TT + t0) * D4 + tid;
        const float4* __restrict__ pq = q + ((size_t)b * TT + t0) * D4 + tid;
        const int n = t1 - t0;
        if (n == CHUNK) {
            // fast path: 8 rows, loads front-batched in groups of 4 rows
            #pragma unroll
            for (int h = 0; h < 2; ++h) {
                float4 A[4], Bv[4];
                #pragma unroll
                for (int i = 0; i < 4; ++i) A[i]  = __ldg(pp + (size_t)(h * 4 + i) * D4);
                #pragma unroll
                for (int i = 0; i < 4; ++i) Bv[i] = __ldg(pq + (size_t)(h * 4 + i) * D4);
                #pragma unroll
                for (int i = 0; i < 4; ++i) {
                    float dx = A[i].x - Bv[i].x, dy = A[i].y - Bv[i].y;
                    float dz = A[i].z - Bv[i].z, dw = A[i].w - Bv[i].w;
                    sd.x += dx; sd.y += dy; sd.z += dz; sd.w += dw;
                    wl += sl1(dx) + sl1(dy) + sl1(dz) + sl1(dw);
                }
            }
        } else {
            for (int i = 0; i < n; ++i) {
                float4 a  = __ldg(pp + (size_t)i * D4);
                float4 bt = __ldg(pq + (size_t)i * D4);
                float dx = a.x - bt.x, dy = a.y - bt.y;
                float dz = a.z - bt.z, dw = a.w - bt.w;
                sd.x += dx; sd.y += dy; sd.z += dz; sd.w += dw;
                wl += sl1(dx) + sl1(dy) + sl1(dz) + sl1(dw);
            }
        }
        g_part[(size_t)blockIdx.x * D4 + tid] = sd;
    }

    // block-reduce word loss (4 warps)
    #pragma unroll
    for (int o = 16; o > 0; o >>= 1) wl += __shfl_down_sync(0xffffffffu, wl, o);
    if ((tid & 31) == 0) s4[tid >> 5] = wl;
    __syncthreads();
    if (tid == 0) g_wl[blockIdx.x] = s4[0] + s4[1] + s4[2] + s4[3];

    // ---------------- Level 1 ticket: last chunk of slab folds it ----------------
    const int slab_id = b * NSLAB + j;
    __threadfence();
    if (tid == 0) {
        int t = atomicAdd(&g_c1[slab_id], 1);
        flag = (t == SLAB - 1);
        if (flag) g_c1[slab_id] = 0;           // unique winner resets for next replay
    }
    __syncthreads();
    if (!flag) return;
    __threadfence();                           // acquire: peers' g_part/g_wl visible

    {
        const float4* __restrict__ base = g_part + ((size_t)(b * NCHUNK + j * SLAB)) * D4 + tid;
        float4 s = make_float4(0.f, 0.f, 0.f, 0.f);
        #pragma unroll
        for (int k = 0; k < SLAB; ++k) {
            float4 a = base[(size_t)k * D4];   // invalid chunks read exact 0.0
            s.x += a.x; s.y += a.y; s.z += a.z; s.w += a.w;
        }
        g_part2[(size_t)slab_id * D4 + tid] = s;
    }
    if (tid < 32) {
        float w = (tid < SLAB) ? g_wl[b * NCHUNK + j * SLAB + tid] : 0.f;
        #pragma unroll
        for (int o = 4; o > 0; o >>= 1) w += __shfl_down_sync(0xffffffffu, w, o);
        if (tid == 0) g_wl2[slab_id] = w;
    }

    // ---------------- Level 2 ticket: last slab of batch folds it ----------------
    __threadfence();
    __syncthreads();
    if (tid == 0) {
        int t = atomicAdd(&g_c2[b], 1);
        flag = (t == NSLAB - 1);
        if (flag) g_c2[b] = 0;
    }
    __syncthreads();
    if (!flag) return;
    __threadfence();

    {
        const float4* __restrict__ b2 = g_part2 + (size_t)b * NSLAB * D4 + tid;
        float4 tot = make_float4(0.f, 0.f, 0.f, 0.f);
        #pragma unroll 8
        for (int k = 0; k < NSLAB; ++k) {
            float4 a = b2[(size_t)k * D4];
            tot.x += a.x; tot.y += a.y; tot.z += a.z; tot.w += a.w;
        }
        float inv_len = 1.0f / (float)len;
        float v = sl1(tot.x * inv_len) + sl1(tot.y * inv_len)
                + sl1(tot.z * inv_len) + sl1(tot.w * inv_len);
        #pragma unroll
        for (int o = 16; o > 0; o >>= 1) v += __shfl_down_sync(0xffffffffu, v, o);
        __syncthreads();                        // s4 reuse barrier
        if ((tid & 31) == 0) s4[tid >> 5] = v;
        __syncthreads();
        if (tid == 0) g_sent[b] = (s4[0] + s4[1] + s4[2] + s4[3]) / (float)DD;
    }
    if (tid < 32) {
        float w = g_wl2[b * NSLAB + tid];
        #pragma unroll
        for (int o = 16; o > 0; o >>= 1) w += __shfl_down_sync(0xffffffffu, w, o);
        if (tid == 0) g_wlb[b] = w;
    }

    // ---------------- Level 3 ticket: last batch writes the output ----------------
    __threadfence();
    __syncthreads();
    if (tid == 0) {
        int t = atomicAdd(&g_c3, 1);
        flag = (t == BB - 1);
        if (flag) g_c3 = 0;
    }
    __syncthreads();
    if (!flag) return;
    __threadfence();

    if (tid < 32) {
        float sn = g_sent[tid];
        float w  = g_wlb[tid];
        float ls = (float)__ldg(lens + tid);
        #pragma unroll
        for (int o = 16; o > 0; o >>= 1) {
            sn += __shfl_down_sync(0xffffffffu, sn, o);
            w  += __shfl_down_sync(0xffffffffu, w,  o);
            ls += __shfl_down_sync(0xffffffffu, ls, o);
        }
        if (tid == 0) {
            float n_valid = ls * (float)DD;
            out[0] = w / n_valid + sn / (float)BB;
        }
    }
}

extern "C" void kernel_launch(void* const* d_in, const int* in_sizes, int n_in,
                              void* d_out, int out_size) {
    const float4* preds   = (const float4*)d_in[0];
    const float4* targets = (const float4*)d_in[1];
    const int*    lens    = (const int*)d_in[2];
    float*        out     = (float*)d_out;

    fused<<<GRID1, 128>>>(preds, targets, lens, out);
}

// round 14
// speedup vs baseline: 1.7440x; 1.1584x over previous
#include <cuda_runtime.h>
#include <cuda_bf16.h>

// Problem shape (fixed by the dataset)
#define BB 32
#define TT 2048
#define DD 512
#define D4 (DD / 4)            // 128 float4 per (b,t) row
#define NCHUNK 256
#define CHUNK (TT / NCHUNK)    // 8 timesteps per block
#define GRID1 (BB * NCHUNK)    // 8192 blocks

// Scratch (device globals, zero-initialized once at module load).
// g_colsum / g_wltot are re-zeroed by pass2 each run (unique writers), so
// every graph replay starts from a clean accumulator. No memset node needed.
__device__ float4 g_colsum[BB * D4];   // per-(b,d4) sum of (p - t), L2-resident (64 KB)
__device__ float  g_wltot;             // global word-loss accumulator
__device__ float  g_sent[BB];          // per-b sentence loss (mean over D)
__device__ int    g_cnt;               // pass2 ticket (self-resetting)

__device__ __forceinline__ float sl1(float d) {
    float ad = fabsf(d);
    return (ad < 1.0f) ? (0.5f * d * d) : (ad - 0.5f);
}

__device__ __forceinline__ void red_add_v4(float4* addr, float4 v) {
    asm volatile("red.global.add.v4.f32 [%0], {%1, %2, %3, %4};"
                 :: "l"(addr), "f"(v.x), "f"(v.y), "f"(v.z), "f"(v.w) : "memory");
}
__device__ __forceinline__ void red_add_f32(float* addr, float v) {
    asm volatile("red.global.add.f32 [%0], %1;" :: "l"(addr), "f"(v) : "memory");
}

// ---------------------------------------------------------------------------
// Pass 1: stream preds/targets once. grid = 8192, block = 128.
// Thread tid owns float4 column tid; folds its chunk partial into g_colsum
// with ONE red.v4 (no scratch write, no fold kernels).
// ---------------------------------------------------------------------------
__global__ __launch_bounds__(128) void pass1(const float4* __restrict__ p,
                                             const float4* __restrict__ q,
                                             const int* __restrict__ lens) {
    const int b   = blockIdx.x >> 8;           // / NCHUNK
    const int c   = blockIdx.x & (NCHUNK - 1);
    const int tid = threadIdx.x;

    const int len = __ldg(lens + b);
    const int t0  = c * CHUNK;
    const int t1  = min(t0 + CHUNK, len);

    float wl = 0.f;

    if (t1 > t0) {
        float4 sd = make_float4(0.f, 0.f, 0.f, 0.f);
        const float4* __restrict__ pp = p + ((size_t)b * TT + t0) * D4 + tid;
        const float4* __restrict__ pq = q + ((size_t)b * TT + t0) * D4 + tid;
        const int n = t1 - t0;
        #pragma unroll 8
        for (int i = 0; i < n; ++i) {
            float4 a  = __ldcs(pp + (size_t)i * D4);   // streaming, evict-first
            float4 bt = __ldcs(pq + (size_t)i * D4);
            float dx = a.x - bt.x, dy = a.y - bt.y;
            float dz = a.z - bt.z, dw = a.w - bt.w;
            sd.x += dx; sd.y += dy; sd.z += dz; sd.w += dw;
            wl += sl1(dx) + sl1(dy) + sl1(dz) + sl1(dw);
        }
        red_add_v4(&g_colsum[b * D4 + tid], sd);
    }

    // block-reduce word loss (4 warps), single scalar red per block
    #pragma unroll
    for (int o = 16; o > 0; o >>= 1) wl += __shfl_down_sync(0xffffffffu, wl, o);
    __shared__ float s4[4];
    if ((tid & 31) == 0) s4[tid >> 5] = wl;
    __syncthreads();
    if (tid == 0) red_add_f32(&g_wltot, s4[0] + s4[1] + s4[2] + s4[3]);
}

// ---------------------------------------------------------------------------
// Pass 2: grid = BB = 32, block = 128. Block b: sentence loss from g_colsum[b],
// then re-zeroes its slice for the next replay. Last block folds everything,
// writes out[0], and resets g_wltot / g_cnt. No spin-waits (deadlock-free).
// ---------------------------------------------------------------------------
__global__ __launch_bounds__(128) void pass2(const int* __restrict__ lens,
                                             float* __restrict__ out) {
    const int b   = blockIdx.x;
    const int tid = threadIdx.x;

    const int len = __ldg(lens + b);
    float4 s = g_colsum[b * D4 + tid];           // pass1 done (kernel boundary)
    g_colsum[b * D4 + tid] = make_float4(0.f, 0.f, 0.f, 0.f);  // clean for next replay

    const float inv_len = 1.0f / (float)len;
    float v = sl1(s.x * inv_len) + sl1(s.y * inv_len)
            + sl1(s.z * inv_len) + sl1(s.w * inv_len);

    #pragma unroll
    for (int o = 16; o > 0; o >>= 1) v += __shfl_down_sync(0xffffffffu, v, o);
    __shared__ float s4[4];
    __shared__ int   is_last;
    if ((tid & 31) == 0) s4[tid >> 5] = v;
    __syncthreads();

    if (tid == 0) {
        g_sent[b] = (s4[0] + s4[1] + s4[2] + s4[3]) / (float)DD;
        __threadfence();
        int t = atomicAdd(&g_cnt, 1);
        is_last = (t == BB - 1);
    }
    __syncthreads();

    if (is_last && tid < 32) {
        __threadfence();                          // acquire: all g_sent visible
        float sn = g_sent[tid];
        float ls = (float)__ldg(lens + tid);
        #pragma unroll
        for (int o = 16; o > 0; o >>= 1) {
            sn += __shfl_down_sync(0xffffffffu, sn, o);
            ls += __shfl_down_sync(0xffffffffu, ls, o);
        }
        if (tid == 0) {
            float wt = g_wltot;                   // all pass1 reds completed
            out[0] = wt / (ls * (float)DD) + sn / (float)BB;
            g_wltot = 0.f;                        // reset for next replay
            g_cnt   = 0;
        }
    }
}

extern "C" void kernel_launch(void* const* d_in, const int* in_sizes, int n_in,
                              void* d_out, int out_size) {
    const float4* preds   = (const float4*)d_in[0];
    const float4* targets = (const float4*)d_in[1];
    const int*    lens    = (const int*)d_in[2];
    float*        out     = (float*)d_out;

    pass1<<<GRID1, 128>>>(preds, targets, lens);
    pass2<<<BB, 128>>>(lens, out);
}

// round 15
// speedup vs baseline: 1.8065x; 1.0359x over previous
#include <cuda_runtime.h>
#include <cuda_bf16.h>

// Problem shape (fixed by the dataset)
#define BB 32
#define TT 2048
#define DD 512
#define D4 (DD / 4)            // 128 float4 per (b,t) row
#define NCHUNK 256
#define CHUNK (TT / NCHUNK)    // 8 timesteps per block
#define GRID1 (BB * NCHUNK)    // 8192 blocks

// Scratch (device globals, zero-initialized at module load).
// g_colsum / g_wltot are re-zeroed by pass2 each run (unique writers), so
// every graph replay starts clean. No memset node needed.
__device__ float4 g_colsum[BB * D4];   // per-(b,d4) sum of (p - t), L2-resident (64 KB)
__device__ float  g_wltot;             // global word-loss accumulator

__device__ __forceinline__ float sl1(float d) {
    float ad = fabsf(d);
    return (ad < 1.0f) ? (0.5f * d * d) : (ad - 0.5f);
}

__device__ __forceinline__ void red_add_v4(float4* addr, float4 v) {
    asm volatile("red.global.add.v4.f32 [%0], {%1, %2, %3, %4};"
                 :: "l"(addr), "f"(v.x), "f"(v.y), "f"(v.z), "f"(v.w) : "memory");
}
__device__ __forceinline__ void red_add_f32(float* addr, float v) {
    asm volatile("red.global.add.f32 [%0], %1;" :: "l"(addr), "f"(v) : "memory");
}

// ---------------------------------------------------------------------------
// Pass 1: stream preds/targets once. grid = 8192, block = 128.
// __launch_bounds__(128, 8): <=64 regs so the explicit 8-load front batches
// survive ptxas (32 warps/SM, ~128KB in flight — well past BW*latency).
// Thread tid owns float4 column tid; folds its chunk partial into g_colsum
// with ONE red.v4; word loss via one scalar red per block.
// ---------------------------------------------------------------------------
__global__ void __launch_bounds__(128, 8)
pass1(const float4* __restrict__ p,
      const float4* __restrict__ q,
      const int* __restrict__ lens) {
    const int b   = blockIdx.x >> 8;           // / NCHUNK
    const int c   = blockIdx.x & (NCHUNK - 1);
    const int tid = threadIdx.x;

    const int len = __ldg(lens + b);
    const int t0  = c * CHUNK;
    const int t1  = min(t0 + CHUNK, len);

    float wl = 0.f;

    if (t1 > t0) {
        float4 sd = make_float4(0.f, 0.f, 0.f, 0.f);
        const float4* __restrict__ pp = p + ((size_t)b * TT + t0) * D4 + tid;
        const float4* __restrict__ pq = q + ((size_t)b * TT + t0) * D4 + tid;
        const int n = t1 - t0;
        if (n == CHUNK) {
            // fast path: 8 rows in two 4-row batches; 8 LDG.128 issued
            // back-to-back before any consumption (32 data regs live).
            #pragma unroll
            for (int h = 0; h < 2; ++h) {
                float4 A0 = __ldcs(pp + (size_t)(h * 4 + 0) * D4);
                float4 A1 = __ldcs(pp + (size_t)(h * 4 + 1) * D4);
                float4 A2 = __ldcs(pp + (size_t)(h * 4 + 2) * D4);
                float4 A3 = __ldcs(pp + (size_t)(h * 4 + 3) * D4);
                float4 B0 = __ldcs(pq + (size_t)(h * 4 + 0) * D4);
                float4 B1 = __ldcs(pq + (size_t)(h * 4 + 1) * D4);
                float4 B2 = __ldcs(pq + (size_t)(h * 4 + 2) * D4);
                float4 B3 = __ldcs(pq + (size_t)(h * 4 + 3) * D4);

                float d0x = A0.x - B0.x, d0y = A0.y - B0.y, d0z = A0.z - B0.z, d0w = A0.w - B0.w;
                float d1x = A1.x - B1.x, d1y = A1.y - B1.y, d1z = A1.z - B1.z, d1w = A1.w - B1.w;
                float d2x = A2.x - B2.x, d2y = A2.y - B2.y, d2z = A2.z - B2.z, d2w = A2.w - B2.w;
                float d3x = A3.x - B3.x, d3y = A3.y - B3.y, d3z = A3.z - B3.z, d3w = A3.w - B3.w;

                sd.x += d0x + d1x + d2x + d3x;
                sd.y += d0y + d1y + d2y + d3y;
                sd.z += d0z + d1z + d2z + d3z;
                sd.w += d0w + d1w + d2w + d3w;

                wl += sl1(d0x) + sl1(d0y) + sl1(d0z) + sl1(d0w)
                    + sl1(d1x) + sl1(d1y) + sl1(d1z) + sl1(d1w)
                    + sl1(d2x) + sl1(d2y) + sl1(d2z) + sl1(d2w)
                    + sl1(d3x) + sl1(d3y) + sl1(d3z) + sl1(d3w);
            }
        } else {
            for (int i = 0; i < n; ++i) {
                float4 a  = __ldcs(pp + (size_t)i * D4);
                float4 bt = __ldcs(pq + (size_t)i * D4);
                float dx = a.x - bt.x, dy = a.y - bt.y;
                float dz = a.z - bt.z, dw = a.w - bt.w;
                sd.x += dx; sd.y += dy; sd.z += dz; sd.w += dw;
                wl += sl1(dx) + sl1(dy) + sl1(dz) + sl1(dw);
            }
        }
        red_add_v4(&g_colsum[b * D4 + tid], sd);
    }

    // block-reduce word loss (4 warps), single scalar red per block
    #pragma unroll
    for (int o = 16; o > 0; o >>= 1) wl += __shfl_down_sync(0xffffffffu, wl, o);
    __shared__ float s4[4];
    if ((tid & 31) == 0) s4[tid >> 5] = wl;
    __syncthreads();
    if (tid == 0) red_add_f32(&g_wltot, s4[0] + s4[1] + s4[2] + s4[3]);
}

// ---------------------------------------------------------------------------
// Pass 2: ONE block, 1024 threads. Warp w = batch b. Each lane reads 4 float4
// of g_colsum[b] (L2-hot), zeroes them for the next replay, computes the
// sentence-loss terms, warp-reduces, then warp 0 folds all 32 batches and
// writes out[0]. No tickets, no fences — kernel boundary orders pass1's reds.
// ---------------------------------------------------------------------------
__global__ void __launch_bounds__(1024)
pass2(const int* __restrict__ lens, float* __restrict__ out) {
    const int tid  = threadIdx.x;
    const int b    = tid >> 5;          // warp = batch
    const int lane = tid & 31;

    float4* base = &g_colsum[b * D4];
    float4 s0 = base[lane];
    float4 s1 = base[lane + 32];
    float4 s2 = base[lane + 64];
    float4 s3 = base[lane + 96];
    const float4 z = make_float4(0.f, 0.f, 0.f, 0.f);
    base[lane] = z; base[lane + 32] = z; base[lane + 64] = z; base[lane + 96] = z;

    const float inv_len = 1.0f / (float)__ldg(lens + b);
    float v = sl1(s0.x * inv_len) + sl1(s0.y * inv_len) + sl1(s0.z * inv_len) + sl1(s0.w * inv_len)
            + sl1(s1.x * inv_len) + sl1(s1.y * inv_len) + sl1(s1.z * inv_len) + sl1(s1.w * inv_len)
            + sl1(s2.x * inv_len) + sl1(s2.y * inv_len) + sl1(s2.z * inv_len) + sl1(s2.w * inv_len)
            + sl1(s3.x * inv_len) + sl1(s3.y * inv_len) + sl1(s3.z * inv_len) + sl1(s3.w * inv_len);

    #pragma unroll
    for (int o = 16; o > 0; o >>= 1) v += __shfl_down_sync(0xffffffffu, v, o);

    __shared__ float ssent[32];
    if (lane == 0) ssent[b] = v / (float)DD;    // mean over D
    __syncthreads();

    if (b == 0) {                                // warp 0 folds everything
        float sn = ssent[lane];
        float ls = (float)__ldg(lens + lane);
        #pragma unroll
        for (int o = 16; o > 0; o >>= 1) {
            sn += __shfl_down_sync(0xffffffffu, sn, o);
            ls += __shfl_down_sync(0xffffffffu, ls, o);
        }
        if (lane == 0) {
            float wt = g_wltot;                  // all pass1 reds complete
            out[0] = wt / (ls * (float)DD) + sn / (float)BB;
            g_wltot = 0.f;                       // reset for next replay
        }
    }
}

extern "C" void kernel_launch(void* const* d_in, const int* in_sizes, int n_in,
                              void* d_out, int out_size) {
    const float4* preds   = (const float4*)d_in[0];
    const float4* targets = (const float4*)d_in[1];
    const int*    lens    = (const int*)d_in[2];
    float*        out     = (float*)d_out;

    pass1<<<GRID1, 128>>>(preds, targets, lens);
    pass2<<<1, 1024>>>(lens, out);
}